// round 15
// baseline (speedup 1.0000x reference)
#include <cuda_runtime.h>
#include <cuda_fp16.h>

// ---------------------------------------------------------------------------
// 2-layer GCN, pull aggregation over per-call CSR-by-dst.
//   g = (h @ W) * dinv[row];  agg[d] = dinv[d]*(sum_in g[src] + g[d])
// GEMM1 tf32 tensor cores. Layer-2 GEMM fused into agg1's epilogue
// (shfl_xor cross-lane reduction; out1 never hits memory).
// g1/g2 fp16 (fp32 accumulate). CSR rank trick (atomic-free fill).
// k_fill || k_gemm1 on forked streams. edge_index dtype probed at runtime.
// ---------------------------------------------------------------------------

#define MAXN 100000
#define MAXE 1600000

__device__ int    d_mode;
__device__ int    d_ctr;
__device__ int    d_counts[MAXN];
__device__ int    d_rowptr[MAXN];
__device__ int    d_rank[MAXE];
__device__ int    d_col[MAXE];
__device__ float  d_dinv[MAXN];
__device__ __half d_g1[MAXN * 128];    // (x@W1)*dinv, fp16
__device__ __half d_g2[MAXN * 16];     // (relu(l1)@W2)*dinv, fp16

// ---------------- zero + dtype probe (fused) ----------------

__global__ void k_zero(const unsigned* __restrict__ ei_w, int n) {
    int i = blockIdx.x * blockDim.x + threadIdx.x;
    if (i < n) d_counts[i] = 0;
    if (i == 0) d_ctr = 0;
    if (blockIdx.x == 0 && threadIdx.x < 32) {
        int l = threadIdx.x;
        unsigned any = 0;
        #pragma unroll
        for (int j = 0; j < 8; j++) any |= ei_w[2 * (l + j * 32) + 1];
        unsigned ball = __ballot_sync(0xFFFFFFFFu, any != 0);
        if (l == 0) d_mode = (ball == 0) ? 1 : 0;
    }
}

__device__ __forceinline__ int load_idx(const void* ei, int e, int which, int i) {
    if (d_mode) return (int)((const long long*)ei)[(long long)which * e + i];
    return ((const int*)ei)[which * e + i];
}

// ------------- degree count + per-edge rank (4 edges per thread) -----------

__global__ void k_deg(const void* __restrict__ ei, int e, int n) {
    int i4 = (blockIdx.x * blockDim.x + threadIdx.x) * 4;
    if (i4 >= e) return;
    if (d_mode == 0 && (e & 3) == 0 && i4 + 4 <= e) {
        int4 d = *(const int4*)((const int*)ei + e + i4);
        int4 r = make_int4(0, 0, 0, 0);
        if ((unsigned)d.x < (unsigned)n) r.x = atomicAdd(&d_counts[d.x], 1);
        if ((unsigned)d.y < (unsigned)n) r.y = atomicAdd(&d_counts[d.y], 1);
        if ((unsigned)d.z < (unsigned)n) r.z = atomicAdd(&d_counts[d.z], 1);
        if ((unsigned)d.w < (unsigned)n) r.w = atomicAdd(&d_counts[d.w], 1);
        *(int4*)&d_rank[i4] = r;
    } else {
        int lim = min(i4 + 4, e);
        for (int j = i4; j < lim; j++) {
            int d = load_idx(ei, e, 1, j);
            int r = 0;
            if ((unsigned)d < (unsigned)n) r = atomicAdd(&d_counts[d], 1);
            d_rank[j] = r;
        }
    }
}

// ---------------- offset allocation: block-aggregated atomic bump ----------

__global__ __launch_bounds__(256) void k_alloc(int n) {
    __shared__ int warp_base[8];
    __shared__ int block_base;
    int tid = threadIdx.x;
    int i = blockIdx.x * 256 + tid;
    int lane = tid & 31, wid = tid >> 5;

    int c = (i < n) ? d_counts[i] : 0;
    if (i < n) d_dinv[i] = rsqrtf((float)(c + 1));

    int pref = c;
    #pragma unroll
    for (int off = 1; off < 32; off <<= 1) {
        int v = __shfl_up_sync(0xFFFFFFFFu, pref, off);
        if (lane >= off) pref += v;
    }
    if (lane == 31) warp_base[wid] = pref;
    __syncthreads();
    if (tid == 0) {
        int s = 0;
        #pragma unroll
        for (int w = 0; w < 8; w++) { int t = warp_base[w]; warp_base[w] = s; s += t; }
        block_base = atomicAdd(&d_ctr, s);
    }
    __syncthreads();
    if (i < n) d_rowptr[i] = block_base + warp_base[wid] + (pref - c);
}

// ---------------- CSR fill: atomic-free via precomputed ranks ----------------

__global__ void k_fill(const void* __restrict__ ei, int e, int n) {
    int i4 = (blockIdx.x * blockDim.x + threadIdx.x) * 4;
    if (i4 >= e) return;
    if (d_mode == 0 && (e & 3) == 0 && i4 + 4 <= e) {
        int4 s = *(const int4*)((const int*)ei + i4);
        int4 d = *(const int4*)((const int*)ei + e + i4);
        int4 r = *(const int4*)&d_rank[i4];
        if ((unsigned)d.x < (unsigned)n && (unsigned)s.x < (unsigned)n)
            d_col[d_rowptr[d.x] + r.x] = s.x;
        if ((unsigned)d.y < (unsigned)n && (unsigned)s.y < (unsigned)n)
            d_col[d_rowptr[d.y] + r.y] = s.y;
        if ((unsigned)d.z < (unsigned)n && (unsigned)s.z < (unsigned)n)
            d_col[d_rowptr[d.z] + r.z] = s.z;
        if ((unsigned)d.w < (unsigned)n && (unsigned)s.w < (unsigned)n)
            d_col[d_rowptr[d.w] + r.w] = s.w;
    } else {
        int lim = min(i4 + 4, e);
        for (int j = i4; j < lim; j++) {
            int s = load_idx(ei, e, 0, j);
            int d = load_idx(ei, e, 1, j);
            if ((unsigned)d < (unsigned)n && (unsigned)s < (unsigned)n)
                d_col[d_rowptr[d] + d_rank[j]] = s;
        }
    }
}

// ---------------- Layer 1 GEMM (tf32 tensor cores) ----------------

__device__ __forceinline__ unsigned f2tf(float f) {
    unsigned u;
    asm("cvt.rna.tf32.f32 %0, %1;" : "=r"(u) : "f"(f));
    return u;
}

__device__ __forceinline__ void mma_tf32(float* d, const unsigned* a, const unsigned* b) {
    asm volatile(
        "mma.sync.aligned.m16n8k8.row.col.f32.tf32.tf32.f32 "
        "{%0,%1,%2,%3}, {%4,%5,%6,%7}, {%8,%9}, {%0,%1,%2,%3};"
        : "+f"(d[0]), "+f"(d[1]), "+f"(d[2]), "+f"(d[3])
        : "r"(a[0]), "r"(a[1]), "r"(a[2]), "r"(a[3]), "r"(b[0]), "r"(b[1]));
}

__global__ __launch_bounds__(256) void k_gemm1_tc(const float* __restrict__ x,
                                                  const float* __restrict__ W1,
                                                  int n) {
    __shared__ float xs[128][36];
    __shared__ float ws[32][136];
    int tid = threadIdx.x;
    int lane = tid & 31;
    int wid = tid >> 5;
    int wm = wid & 1;
    int wn = wid >> 1;
    int row0 = blockIdx.x * 128;

    float acc[4][4][4];
    #pragma unroll
    for (int i = 0; i < 4; i++)
        #pragma unroll
        for (int j = 0; j < 4; j++)
            #pragma unroll
            for (int r = 0; r < 4; r++) acc[i][j][r] = 0.f;

    for (int k0 = 0; k0 < 256; k0 += 32) {
        if (k0) __syncthreads();
        #pragma unroll
        for (int i = 0; i < 4; i++) {
            int f = tid + i * 256;
            int r = f >> 3;
            int c = (f & 7) * 4;
            float4 v = make_float4(0.f, 0.f, 0.f, 0.f);
            if (row0 + r < n) v = *(const float4*)&x[(row0 + r) * 256 + k0 + c];
            xs[r][c] = v.x; xs[r][c + 1] = v.y; xs[r][c + 2] = v.z; xs[r][c + 3] = v.w;
        }
        #pragma unroll
        for (int i = 0; i < 4; i++) {
            int f = tid + i * 256;
            int kk = f >> 5;
            int c = (f & 31) * 4;
            float4 v = *(const float4*)&W1[(k0 + kk) * 128 + c];
            ws[kk][c] = v.x; ws[kk][c + 1] = v.y; ws[kk][c + 2] = v.z; ws[kk][c + 3] = v.w;
        }
        __syncthreads();

        #pragma unroll
        for (int ks = 0; ks < 4; ks++) {
            int k = ks * 8;
            unsigned a[4][4], b[4][2];
            int ar = lane >> 2;
            int ac = k + (lane & 3);
            #pragma unroll
            for (int mf = 0; mf < 4; mf++) {
                int r = wm * 64 + mf * 16 + ar;
                a[mf][0] = f2tf(xs[r][ac]);
                a[mf][1] = f2tf(xs[r + 8][ac]);
                a[mf][2] = f2tf(xs[r][ac + 4]);
                a[mf][3] = f2tf(xs[r + 8][ac + 4]);
            }
            int bc = wn * 32 + (lane >> 2);
            int br = k + (lane & 3);
            #pragma unroll
            for (int nf = 0; nf < 4; nf++) {
                b[nf][0] = f2tf(ws[br][bc + nf * 8]);
                b[nf][1] = f2tf(ws[br + 4][bc + nf * 8]);
            }
            #pragma unroll
            for (int mf = 0; mf < 4; mf++)
                #pragma unroll
                for (int nf = 0; nf < 4; nf++)
                    mma_tf32(acc[mf][nf], a[mf], b[nf]);
        }
    }

    #pragma unroll
    for (int mf = 0; mf < 4; mf++) {
        int r0 = row0 + wm * 64 + mf * 16 + (lane >> 2);
        int r1 = r0 + 8;
        float s0 = (r0 < n) ? d_dinv[r0] : 0.f;
        float s1 = (r1 < n) ? d_dinv[r1] : 0.f;
        #pragma unroll
        for (int nf = 0; nf < 4; nf++) {
            int c = wn * 32 + nf * 8 + (lane & 3) * 2;
            if (r0 < n)
                *(__half2*)&d_g1[r0 * 128 + c] =
                    __floats2half2_rn(acc[mf][nf][0] * s0, acc[mf][nf][1] * s0);
            if (r1 < n)
                *(__half2*)&d_g1[r1 * 128 + c] =
                    __floats2half2_rn(acc[mf][nf][2] * s1, acc[mf][nf][3] * s1);
        }
    }
}

// ---------------- fp16 helpers ----------------

__device__ __forceinline__ void acc_u4(float* acc, uint4 u) {
    float2 f0 = __half22float2(*(__half2*)&u.x);
    float2 f1 = __half22float2(*(__half2*)&u.y);
    float2 f2 = __half22float2(*(__half2*)&u.z);
    float2 f3 = __half22float2(*(__half2*)&u.w);
    acc[0] += f0.x; acc[1] += f0.y; acc[2] += f1.x; acc[3] += f1.y;
    acc[4] += f2.x; acc[5] += f2.y; acc[6] += f3.x; acc[7] += f3.y;
}

__device__ __forceinline__ float4 ld_g2h(int row, int part) {
    uint2 u = *(const uint2*)(d_g2 + row * 16 + part * 4);
    float2 f0 = __half22float2(*(__half2*)&u.x);
    float2 f1 = __half22float2(*(__half2*)&u.y);
    return make_float4(f0.x, f0.y, f1.x, f1.y);
}

// ------ Layer 1 aggregation + fused layer-2 GEMM: half-warp per node ------
// 16 lanes per node, 8 features/lane. After aggregating out1 features in
// registers, compute g2 = dinv*(relu(out1)@W2) via per-lane partial dot
// products + shfl_xor reduction across the 16 lanes. out1 never stored.

__global__ __launch_bounds__(256) void k_agg1_fused(const float* __restrict__ b1,
                                                    const float* __restrict__ W2,
                                                    int n) {
    __shared__ float w2s[128][17];   // W2 padded
    {
        int tid = threadIdx.x;
        #pragma unroll
        for (int i = 0; i < 8; i++) {
            int idx = tid + i * 256;   // 2048 floats
            w2s[idx >> 4][idx & 15] = W2[idx];
        }
    }
    __syncthreads();

    int gw = (blockIdx.x * 256 + threadIdx.x) >> 4;
    int sl = threadIdx.x & 15;
    if (gw >= n) return;
    const __half* g1 = d_g1;
    int fo = sl * 8;

    float acc[8] = {};
    acc_u4(acc, *(const uint4*)(g1 + gw * 128 + fo));  // self-loop

    int e = d_rowptr[gw], end = e + d_counts[gw];
    for (; e + 8 <= end; e += 8) {
        int s0 = d_col[e],     s1 = d_col[e + 1], s2 = d_col[e + 2], s3 = d_col[e + 3];
        int s4 = d_col[e + 4], s5 = d_col[e + 5], s6 = d_col[e + 6], s7 = d_col[e + 7];
        uint4 u0 = *(const uint4*)(g1 + s0 * 128 + fo);
        uint4 u1 = *(const uint4*)(g1 + s1 * 128 + fo);
        uint4 u2 = *(const uint4*)(g1 + s2 * 128 + fo);
        uint4 u3 = *(const uint4*)(g1 + s3 * 128 + fo);
        uint4 u4 = *(const uint4*)(g1 + s4 * 128 + fo);
        uint4 u5 = *(const uint4*)(g1 + s5 * 128 + fo);
        uint4 u6 = *(const uint4*)(g1 + s6 * 128 + fo);
        uint4 u7 = *(const uint4*)(g1 + s7 * 128 + fo);
        acc_u4(acc, u0); acc_u4(acc, u1); acc_u4(acc, u2); acc_u4(acc, u3);
        acc_u4(acc, u4); acc_u4(acc, u5); acc_u4(acc, u6); acc_u4(acc, u7);
    }
    for (; e < end; e++)
        acc_u4(acc, *(const uint4*)(g1 + d_col[e] * 128 + fo));

    float sc = d_dinv[gw];
    float4 bb0 = ((const float4*)b1)[sl * 2];
    float4 bb1 = ((const float4*)b1)[sl * 2 + 1];
    float o[8];
    o[0] = fmaxf(fmaf(sc, acc[0], bb0.x), 0.f);
    o[1] = fmaxf(fmaf(sc, acc[1], bb0.y), 0.f);
    o[2] = fmaxf(fmaf(sc, acc[2], bb0.z), 0.f);
    o[3] = fmaxf(fmaf(sc, acc[3], bb0.w), 0.f);
    o[4] = fmaxf(fmaf(sc, acc[4], bb1.x), 0.f);
    o[5] = fmaxf(fmaf(sc, acc[5], bb1.y), 0.f);
    o[6] = fmaxf(fmaf(sc, acc[6], bb1.z), 0.f);
    o[7] = fmaxf(fmaf(sc, acc[7], bb1.w), 0.f);

    // per-lane partial dot products against W2[fo..fo+8][0..16]
    float p[16] = {};
    #pragma unroll
    for (int j = 0; j < 8; j++) {
        float oj = o[j];
        const float* wr = &w2s[fo + j][0];
        #pragma unroll
        for (int c = 0; c < 16; c++) p[c] = fmaf(oj, wr[c], p[c]);
    }
    // reduce across 16 lanes (xor offsets stay within aligned 16-lane groups)
    #pragma unroll
    for (int off = 8; off > 0; off >>= 1) {
        #pragma unroll
        for (int c = 0; c < 16; c++)
            p[c] += __shfl_xor_sync(0xFFFFFFFFu, p[c], off);
    }
    // lanes 0..7 each write one half2 of g2 (scaled by this row's dinv)
    if (sl < 8) {
        __half2 h = __floats2half2_rn(p[2 * sl] * sc, p[2 * sl + 1] * sc);
        *(__half2*)&d_g2[gw * 16 + 2 * sl] = h;
    }
}

// ---------------- Layer 2 aggregation + final output (unroll 8) ------------

__global__ __launch_bounds__(256) void k_agg2(const float* __restrict__ b2,
                                              float* __restrict__ out, int n) {
    int t = blockIdx.x * blockDim.x + threadIdx.x;
    int row = t >> 2;
    int part = t & 3;
    if (row >= n) return;
    float4 acc = ld_g2h(row, part);
    int e = d_rowptr[row], end = e + d_counts[row];
    for (; e + 8 <= end; e += 8) {
        int s0 = d_col[e],     s1 = d_col[e + 1], s2 = d_col[e + 2], s3 = d_col[e + 3];
        int s4 = d_col[e + 4], s5 = d_col[e + 5], s6 = d_col[e + 6], s7 = d_col[e + 7];
        float4 v0 = ld_g2h(s0, part);
        float4 v1 = ld_g2h(s1, part);
        float4 v2 = ld_g2h(s2, part);
        float4 v3 = ld_g2h(s3, part);
        float4 v4 = ld_g2h(s4, part);
        float4 v5 = ld_g2h(s5, part);
        float4 v6 = ld_g2h(s6, part);
        float4 v7 = ld_g2h(s7, part);
        acc.x += ((v0.x + v1.x) + (v2.x + v3.x)) + ((v4.x + v5.x) + (v6.x + v7.x));
        acc.y += ((v0.y + v1.y) + (v2.y + v3.y)) + ((v4.y + v5.y) + (v6.y + v7.y));
        acc.z += ((v0.z + v1.z) + (v2.z + v3.z)) + ((v4.z + v5.z) + (v6.z + v7.z));
        acc.w += ((v0.w + v1.w) + (v2.w + v3.w)) + ((v4.w + v5.w) + (v6.w + v7.w));
    }
    for (; e < end; e++) {
        float4 v = ld_g2h(d_col[e], part);
        acc.x += v.x; acc.y += v.y; acc.z += v.z; acc.w += v.w;
    }
    float sc = d_dinv[row];
    float4 bb = ((const float4*)b2)[part];
    float4 o;
    o.x = fmaf(sc, acc.x, bb.x);
    o.y = fmaf(sc, acc.y, bb.y);
    o.z = fmaf(sc, acc.z, bb.z);
    o.w = fmaf(sc, acc.w, bb.w);
    *(float4*)&out[row * 16 + part * 4] = o;
}

// ---------------- launch: fork k_fill || k_gemm1 ----------------

extern "C" void kernel_launch(void* const* d_in, const int* in_sizes, int n_in,
                              void* d_out, int out_size) {
    const float* x  = (const float*)d_in[0];
    const void*  ei = d_in[1];
    const float* W1 = (const float*)d_in[2];
    const float* b1 = (const float*)d_in[3];
    const float* W2 = (const float*)d_in[4];
    const float* b2 = (const float*)d_in[5];
    float* out = (float*)d_out;

    int n = in_sizes[0] / 256;
    int e = in_sizes[1] / 2;
    int nv = (e + 3) / 4;

    cudaStream_t s2;
    cudaStreamCreateWithFlags(&s2, cudaStreamNonBlocking);
    cudaEvent_t ev_fork, ev_join;
    cudaEventCreateWithFlags(&ev_fork, cudaEventDisableTiming);
    cudaEventCreateWithFlags(&ev_join, cudaEventDisableTiming);

    k_zero <<<(n + 255) / 256, 256>>>((const unsigned*)ei, n);
    k_deg  <<<(nv + 255) / 256, 256>>>(ei, e, n);
    k_alloc<<<(n + 255) / 256, 256>>>(n);

    cudaEventRecord(ev_fork, 0);
    cudaStreamWaitEvent(s2, ev_fork, 0);
    k_fill <<<(nv + 255) / 256, 256>>>(ei, e, n);
    k_gemm1_tc<<<(n + 127) / 128, 256, 0, s2>>>(x, W1, n);
    cudaEventRecord(ev_join, s2);
    cudaStreamWaitEvent(0, ev_join, 0);

    k_agg1_fused<<<(n * 16 + 255) / 256, 256>>>(b1, W2, n);
    k_agg2 <<<(n * 4 + 255) / 256, 256>>>(b2, out, n);

    cudaEventDestroy(ev_fork);
    cudaEventDestroy(ev_join);
    cudaStreamDestroy(s2);
}